// round 16
// baseline (speedup 1.0000x reference)
#include <cuda_runtime.h>
#include <cuda_bf16.h>
#include <cstdint>

// Problem constants
#define BB 4
#define TT 512
#define HH 256
#define EE 256
#define VV 32000
#define BT (BB*TT)          // 2048

// ---------------- device scratch (no cudaMalloc allowed) ----------------
__device__ float g_xp[BT * 768];          // [B*T, 3H]
__device__ float g_combined[BT * 512];    // [:, :256] = gru out (cols 256+ unused now)
__device__ float g_q[BT * HH];
__device__ float g_k[BT * HH];
__device__ float g_h[BB * HH];            // h0 in, h_last out

// split-bf16 operands for the HMMA FC
__device__ __align__(256) __nv_bfloat16 g_Whi[(size_t)VV * 512];
__device__ __align__(256) __nv_bfloat16 g_Wlo[(size_t)VV * 512];
__device__ __align__(256) __nv_bfloat16 g_Ahi[(size_t)BT * 512];
__device__ __align__(256) __nv_bfloat16 g_Alo[(size_t)BT * 512];

typedef unsigned long long u64;

__device__ __forceinline__ float tanh_fast(float x) {
    float y; asm("tanh.approx.f32 %0, %1;" : "=f"(y) : "f"(x)); return y;
}
__device__ __forceinline__ uint32_t smem_u32(const void* p) {
    uint32_t a;
    asm("{ .reg .u64 t; cvta.to.shared.u64 t, %1; cvt.u32.u64 %0, t; }" : "=r"(a) : "l"(p));
    return a;
}
__device__ __forceinline__ u64 pack2(float lo, float hi) {
    u64 r; asm("mov.b64 %0, {%1,%2};" : "=l"(r) : "f"(lo), "f"(hi)); return r;
}
__device__ __forceinline__ void unpack2(u64 v, float& lo, float& hi) {
    asm("mov.b64 {%0,%1}, %2;" : "=f"(lo), "=f"(hi) : "l"(v));
}
__device__ __forceinline__ u64 ffma2(u64 a, u64 b, u64 c) {
    u64 d; asm("fma.rn.f32x2 %0, %1, %2, %3;" : "=l"(d) : "l"(a), "l"(b), "l"(c)); return d;
}

// ---------------- init: h0 <- input h ----------------
__global__ void init_kernel(const float* __restrict__ h_in) {
    int t = threadIdx.x;
    if (t < BB * HH) g_h[t] = h_in[t];
}

// ---------------- generic small GEMM: C[M,N] = A[M,K] @ B[N,K]^T + bias ----------------
__global__ void __launch_bounds__(256) gemm_nt(
    const float* __restrict__ A, int lda, const int* __restrict__ idx,
    const float* __restrict__ B, int K,
    const float* __restrict__ bias, float* __restrict__ C, int ldc)
{
    __shared__ float As[32 * 68];
    __shared__ float Bs[32 * 68];
    const int tid = threadIdx.x;
    const int m0 = blockIdx.y * 64, n0 = blockIdx.x * 64;
    const int tx = tid & 15, ty = tid >> 4;
    const int mt = ty * 4, nt = tx * 4;

    float acc[4][4];
#pragma unroll
    for (int i = 0; i < 4; i++)
#pragma unroll
        for (int j = 0; j < 4; j++) acc[i][j] = 0.f;

    const int kt_n = K >> 5;
    for (int kt = 0; kt < kt_n; kt++) {
        const int k0 = kt * 32;
#pragma unroll
        for (int rep = 0; rep < 2; rep++) {
            int f = tid + rep * 256;
            int row = f >> 3, kq = f & 7;
            int ar = m0 + row;
            if (idx) ar = __ldg(&idx[ar]);
            float4 av = __ldg((const float4*)(A + (size_t)ar * lda + k0 + kq * 4));
            float4 bv = __ldg((const float4*)(B + (size_t)(n0 + row) * K + k0 + kq * 4));
            As[(kq * 4 + 0) * 68 + row] = av.x;
            As[(kq * 4 + 1) * 68 + row] = av.y;
            As[(kq * 4 + 2) * 68 + row] = av.z;
            As[(kq * 4 + 3) * 68 + row] = av.w;
            Bs[(kq * 4 + 0) * 68 + row] = bv.x;
            Bs[(kq * 4 + 1) * 68 + row] = bv.y;
            Bs[(kq * 4 + 2) * 68 + row] = bv.z;
            Bs[(kq * 4 + 3) * 68 + row] = bv.w;
        }
        __syncthreads();
#pragma unroll
        for (int k = 0; k < 32; k++) {
            float4 a4 = *(const float4*)(As + k * 68 + mt);
            float4 b4 = *(const float4*)(Bs + k * 68 + nt);
            float am[4] = {a4.x, a4.y, a4.z, a4.w};
            float bn[4] = {b4.x, b4.y, b4.z, b4.w};
#pragma unroll
            for (int i = 0; i < 4; i++)
#pragma unroll
                for (int j = 0; j < 4; j++) acc[i][j] = fmaf(am[i], bn[j], acc[i][j]);
        }
        __syncthreads();
    }
    float4 b4 = __ldg((const float4*)(bias + n0 + nt));
#pragma unroll
    for (int i = 0; i < 4; i++) {
        float4 r;
        r.x = acc[i][0] + b4.x; r.y = acc[i][1] + b4.y;
        r.z = acc[i][2] + b4.z; r.w = acc[i][3] + b4.w;
        *(float4*)(C + (size_t)(m0 + mt + i) * ldc + n0 + nt) = r;
    }
}

// ---------------- GRU: 4 clusters x 8 CTAs, warp-local pipeline + mbarrier sync ----
// Thread (d, o): all 3 gates for dim d over cols [32o, 32o+32). Per-step sync is an
// mbarrier phase barrier (count 256 = 8 CTAs x 32 store-threads): stores ->
// __syncthreads (readers done, CTA scope) -> o==0 threads arrive.release.cluster on
// all 8 CTAs -> all threads try_wait.acquire.cluster (~60-90 cyc vs UCGABAR ~490).
__global__ void __launch_bounds__(256, 1) __cluster_dims__(8, 1, 1)
gru_kernel(const float* __restrict__ w_hh, const float* __restrict__ b_hh)
{
    __shared__ __align__(16) float hsm[2][8 * 36];   // octant-strided, double-buffered
    __shared__ __align__(8) u64 mbar;

    const int tid = threadIdx.x;
    const int batch = blockIdx.x >> 3;
    const int rank = blockIdx.x & 7;
    const int d = tid >> 3;          // dim within CTA
    const int o = tid & 7;           // octant (32 cols)
    const int dim0 = rank * 32;
    const uint32_t mbar_addr = smem_u32(&mbar);

    if (tid == 0)
        asm volatile("mbarrier.init.shared.b64 [%0], %1;"
                     :: "r"(mbar_addr), "r"(256) : "memory");

    // weights: 3 gates x 32 cols each, packed f32x2 (96 regs)
    u64 w2[48];
#pragma unroll
    for (int g = 0; g < 3; g++) {
        const float4* ws =
            (const float4*)(w_hh + (size_t)(g * 256 + dim0 + d) * 256 + o * 32);
#pragma unroll
        for (int c = 0; c < 8; c++) {
            float4 v = __ldg(&ws[c]);
            w2[g * 16 + 2 * c]     = pack2(v.x, v.y);
            w2[g * 16 + 2 * c + 1] = pack2(v.z, v.w);
        }
    }
    const float bhr = __ldg(&b_hh[0 * 256 + dim0 + d]);
    const float bhz = __ldg(&b_hh[1 * 256 + dim0 + d]);
    const float bhn = __ldg(&b_hh[2 * 256 + dim0 + d]);

    // initial h -> hsm[0]
    for (int idx = tid; idx < HH; idx += 256)
        hsm[0][(idx >> 5) * 36 + (idx & 31)] = g_h[batch * HH + idx];

    const int myd = dim0 + d;
    const int slot = (myd >> 5) * 36 + (myd & 31);
    float xr = 0.f, xz = 0.f, xn = 0.f;
    if (o == 0) {                    // prefetch xp for t=0
        const float* xp = g_xp + (size_t)(batch * TT) * 768 + myd;
        xr = __ldg(xp); xz = __ldg(xp + 256); xn = __ldg(xp + 512);
    }
    __syncthreads();
    // cluster-wide: all mbarriers initialized before any remote arrive can land
    asm volatile("barrier.cluster.arrive.aligned;" ::: "memory");
    asm volatile("barrier.cluster.wait.aligned;" ::: "memory");

    int phase = 0;
    for (int t = 0; t < TT; t++) {
        const int rb = t & 1, wb = rb ^ 1;

        // my 32-col slice of h: 8 conflict-free LDS.128
        u64 hv[16];
        {
            const ulonglong2* hs2 = (const ulonglong2*)(hsm[rb] + o * 36);
#pragma unroll
            for (int c = 0; c < 8; c++) {
                ulonglong2 p = hs2[c];
                hv[2 * c] = p.x; hv[2 * c + 1] = p.y;
            }
        }
        const float hold = hsm[rb][slot];

        u64 ar0 = 0, ar1 = 0, az0 = 0, az1 = 0, an0 = 0, an1 = 0;
#pragma unroll
        for (int c = 0; c < 16; c += 2) {
            ar0 = ffma2(w2[c],          hv[c],     ar0);
            ar1 = ffma2(w2[c + 1],      hv[c + 1], ar1);
            az0 = ffma2(w2[16 + c],     hv[c],     az0);
            az1 = ffma2(w2[16 + c + 1], hv[c + 1], az1);
            an0 = ffma2(w2[32 + c],     hv[c],     an0);
            an1 = ffma2(w2[32 + c + 1], hv[c + 1], an1);
        }
        float p0, p1, p2, p3;
        unpack2(ar0, p0, p1); unpack2(ar1, p2, p3);
        float sr = (p0 + p1) + (p2 + p3);
        unpack2(az0, p0, p1); unpack2(az1, p2, p3);
        float sz = (p0 + p1) + (p2 + p3);
        unpack2(an0, p0, p1); unpack2(an1, p2, p3);
        float sn = (p0 + p1) + (p2 + p3);
#pragma unroll
        for (int off = 1; off < 8; off <<= 1) {
            sr += __shfl_xor_sync(0xffffffffu, sr, off);
            sz += __shfl_xor_sync(0xffffffffu, sz, off);
            sn += __shfl_xor_sync(0xffffffffu, sn, off);
        }

        if (o == 0) {
            const float hr = sr + bhr, hz = sz + bhz, hn = sn + bhn;
            const float r = fmaf(0.5f, tanh_fast(0.5f * (xr + hr)), 0.5f);
            const float z = fmaf(0.5f, tanh_fast(0.5f * (xz + hz)), 0.5f);
            const float n = tanh_fast(fmaf(r, hn, xn));
            const float hnew = fmaf(z, hold - n, n);    // (1-z)*n + z*h
            const size_t row = (size_t)(batch * TT + t) * 512 + myd;
            g_combined[row] = hnew;
            // FC operands written directly (convA eliminated)
            const __nv_bfloat16 bh = __float2bfloat16(hnew);
            const __nv_bfloat16 bl = __float2bfloat16(hnew - __bfloat162float(bh));
            g_Ahi[row] = bh;
            g_Alo[row] = bl;

            // broadcast to hsm[wb] of all 8 cluster CTAs (disjoint slots)
            const uint32_t laddr = smem_u32(&hsm[wb][slot]);
#pragma unroll
            for (int pr = 0; pr < 8; pr++) {
                uint32_t raddr;
                asm("mapa.shared::cluster.u32 %0, %1, %2;"
                    : "=r"(raddr) : "r"(laddr), "r"(pr));
                asm volatile("st.shared::cluster.f32 [%0], %1;"
                             :: "r"(raddr), "f"(hnew));
            }
            if (t + 1 < TT) {                  // prefetch next xp
                const float* xp = g_xp + (size_t)(batch * TT + t + 1) * 768 + myd;
                xr = __ldg(xp); xz = __ldg(xp + 256); xn = __ldg(xp + 512);
            }
        }
        // all CTA threads done reading hsm[rb] (CTA scope)
        __syncthreads();
        // store-threads publish: release their DSMEM stores at cluster scope
        if (o == 0) {
#pragma unroll
            for (int pr = 0; pr < 8; pr++) {
                uint32_t raddr;
                asm("mapa.shared::cluster.u32 %0, %1, %2;"
                    : "=r"(raddr) : "r"(mbar_addr), "r"(pr));
                asm volatile("mbarrier.arrive.release.cluster.shared::cluster.b64 _, [%0];"
                             :: "r"(raddr) : "memory");
            }
        }
        // everyone waits for all 256 arrivals of this phase
        {
            uint32_t done;
            do {
                asm volatile(
                    "{\n\t.reg .pred p;\n\t"
                    "mbarrier.try_wait.parity.acquire.cluster.shared::cta.b64 p, [%1], %2, 0x989680;\n\t"
                    "selp.b32 %0, 1, 0, p;\n\t}"
                    : "=r"(done) : "r"(mbar_addr), "r"((uint32_t)phase) : "memory");
            } while (!done);
        }
        phase ^= 1;
    }

    if (o == 0)                                // step TT lands in buffer 0
        g_h[batch * HH + myd] = hsm[0][slot];
}

// ---------------- attention (ctx written straight to Ahi/Alo) ----------------
__global__ void __launch_bounds__(256) attn_kernel(
    const float* __restrict__ vW, const float* __restrict__ vb)
{
    __shared__ float tile[16 * 256];
    __shared__ float sc[8][512];

    const int tid = threadIdx.x;
    const int w = tid >> 5, lane = tid & 31;
    const int b = blockIdx.y, it = blockIdx.x;
    const int i = it * 8 + w;

    const float4* q4 = (const float4*)(g_q + (size_t)(b * TT + i) * HH + lane * 8);
    const float4 q0 = __ldg(q4), q1 = __ldg(q4 + 1);
    const float4* v4 = (const float4*)(vW + lane * 8);
    const float4 v0 = __ldg(v4), v1 = __ldg(v4 + 1);
    const float vbias = __ldg(vb);

    const int imax = it * 8 + 7;
    const int ntiles = (imax >> 4) + 1;

    for (int jt = 0; jt < ntiles; jt++) {
        const int j0 = jt * 16;
        float4* t4 = (float4*)tile;
#pragma unroll
        for (int rep = 0; rep < 4; rep++) {
            int f = tid + rep * 256;
            int row = f >> 6, c4 = f & 63;
            t4[f] = __ldg((const float4*)g_k + (size_t)(b * TT + j0 + row) * 64 + c4);
        }
        __syncthreads();
#pragma unroll 4
        for (int jj = 0; jj < 16; jj++) {
            int j = j0 + jj;
            if (j <= i) {
                const float4* kr = (const float4*)(tile + jj * 256) + lane * 2;
                float4 k0 = kr[0], k1 = kr[1];
                float s;
                s = v0.x * tanh_fast(q0.x + k0.x);
                s = fmaf(v0.y, tanh_fast(q0.y + k0.y), s);
                s = fmaf(v0.z, tanh_fast(q0.z + k0.z), s);
                s = fmaf(v0.w, tanh_fast(q0.w + k0.w), s);
                s = fmaf(v1.x, tanh_fast(q1.x + k1.x), s);
                s = fmaf(v1.y, tanh_fast(q1.y + k1.y), s);
                s = fmaf(v1.z, tanh_fast(q1.z + k1.z), s);
                s = fmaf(v1.w, tanh_fast(q1.w + k1.w), s);
#pragma unroll
                for (int o = 16; o > 0; o >>= 1) s += __shfl_xor_sync(0xffffffffu, s, o);
                if (lane == 0) sc[w][j] = s + vbias;
            }
        }
        __syncthreads();
    }

    float m = -1e30f;
    for (int j = lane; j <= i; j += 32) m = fmaxf(m, sc[w][j]);
#pragma unroll
    for (int o = 16; o > 0; o >>= 1) m = fmaxf(m, __shfl_xor_sync(0xffffffffu, m, o));
    float sum = 0.f;
    for (int j = lane; j <= i; j += 32) {
        float p = __expf(sc[w][j] - m);
        sc[w][j] = p;
        sum += p;
    }
#pragma unroll
    for (int o = 16; o > 0; o >>= 1) sum += __shfl_xor_sync(0xffffffffu, sum, o);
    const float inv = 1.f / sum;
    __syncthreads();

    float a0 = 0, a1 = 0, a2 = 0, a3 = 0, a4 = 0, a5 = 0, a6 = 0, a7 = 0;
    for (int jt = 0; jt < ntiles; jt++) {
        const int j0 = jt * 16;
        float4* t4 = (float4*)tile;
#pragma unroll
        for (int rep = 0; rep < 4; rep++) {
            int f = tid + rep * 256;
            int row = f >> 6, c4 = f & 63;
            t4[f] = __ldg((const float4*)g_combined + (size_t)(b * TT + j0 + row) * 128 + c4);
        }
        __syncthreads();
#pragma unroll 4
        for (int jj = 0; jj < 16; jj++) {
            int j = j0 + jj;
            if (j <= i) {
                float p = sc[w][j];
                const float4* orow = (const float4*)(tile + jj * 256) + lane * 2;
                float4 o0 = orow[0], o1 = orow[1];
                a0 = fmaf(p, o0.x, a0); a1 = fmaf(p, o0.y, a1);
                a2 = fmaf(p, o0.z, a2); a3 = fmaf(p, o0.w, a3);
                a4 = fmaf(p, o1.x, a4); a5 = fmaf(p, o1.y, a5);
                a6 = fmaf(p, o1.z, a6); a7 = fmaf(p, o1.w, a7);
            }
        }
        __syncthreads();
    }
    // ctx -> split-bf16 FC operands directly (cols 256..511)
    float vals[8] = {a0 * inv, a1 * inv, a2 * inv, a3 * inv,
                     a4 * inv, a5 * inv, a6 * inv, a7 * inv};
    __nv_bfloat16 hi[8], lo[8];
#pragma unroll
    for (int j = 0; j < 8; j++) {
        hi[j] = __float2bfloat16(vals[j]);
        lo[j] = __float2bfloat16(vals[j] - __bfloat162float(hi[j]));
    }
    const size_t off = (size_t)(b * TT + i) * 512 + 256 + lane * 8;
    *(uint4*)(g_Ahi + off) = *(uint4*)hi;
    *(uint4*)(g_Alo + off) = *(uint4*)lo;
}

// ---------------- W split-bf16 conversion ----------------
__global__ void __launch_bounds__(256) convW_kernel(const float* __restrict__ W) {
    size_t i = ((size_t)blockIdx.x * 256 + threadIdx.x) * 4;
    float4 v = __ldg((const float4*)(W + i));
    __nv_bfloat16 h[4], l[4];
    float x[4] = {v.x, v.y, v.z, v.w};
#pragma unroll
    for (int j = 0; j < 4; j++) {
        h[j] = __float2bfloat16(x[j]);
        l[j] = __float2bfloat16(x[j] - __bfloat162float(h[j]));
    }
    *(uint2*)(g_Whi + i) = *(uint2*)h;
    *(uint2*)(g_Wlo + i) = *(uint2*)l;
}

// ---------------- FC via mma.sync HMMA, 4-stage cp.async ring ----------------
// C[2048,32000] = Ahi@Whi^T + Ahi@Wlo^T + Alo@Whi^T + bias  (split-bf16, fp32 accum).
// CTA 128x128x32, 256 threads, warp tile 64x32, 2 CTAs/SM, 4 smem stages.
#define FC_BM 128
#define FC_BN 128
#define ROWB 80
#define FC_STAGE ((FC_BM + FC_BN) * ROWB)      // 20480
#define FC_NSTG 4
#define FC_SMEM (FC_NSTG * FC_STAGE)           // 81920

__device__ __forceinline__ void ldmatrix_x4(uint32_t& r0, uint32_t& r1, uint32_t& r2,
                                            uint32_t& r3, uint32_t addr) {
    asm volatile("ldmatrix.sync.aligned.m8n8.x4.shared.b16 {%0,%1,%2,%3}, [%4];"
                 : "=r"(r0), "=r"(r1), "=r"(r2), "=r"(r3) : "r"(addr));
}
__device__ __forceinline__ void mma16816(float* d, const uint32_t* a, const uint32_t* b) {
    asm volatile(
        "mma.sync.aligned.m16n8k16.row.col.f32.bf16.bf16.f32 "
        "{%0,%1,%2,%3}, {%4,%5,%6,%7}, {%8,%9}, {%0,%1,%2,%3};"
        : "+f"(d[0]), "+f"(d[1]), "+f"(d[2]), "+f"(d[3])
        : "r"(a[0]), "r"(a[1]), "r"(a[2]), "r"(a[3]), "r"(b[0]), "r"(b[1]));
}
__device__ __forceinline__ void cp_async16(uint32_t dst, const void* src) {
    asm volatile("cp.async.cg.shared.global [%0], [%1], 16;" :: "r"(dst), "l"(src));
}

__global__ void __launch_bounds__(256, 2) fc_mma_kernel(
    const float* __restrict__ bias, float* __restrict__ C)
{
    extern __shared__ __align__(128) char smem[];
    const int tid = threadIdx.x;
    const int lane = tid & 31, warp = tid >> 5;
    const int wm = warp >> 2, wn = warp & 3;
    const int mBase = wm * 64, nBase = wn * 32;
    const int m0 = blockIdx.y * FC_BM, n0 = blockIdx.x * FC_BN;
    const uint32_t sm_base = smem_u32(smem);

    float acc[4][4][4];
#pragma unroll
    for (int i = 0; i < 4; i++)
#pragma unroll
        for (int j = 0; j < 4; j++)
#pragma unroll
            for (int r = 0; r < 4; r++) acc[i][j][r] = 0.f;

    auto load_stage = [&](int kc, int buf) {
        const int s = kc >> 4;
        const int kloc = (kc & 15) * 32;
        const __nv_bfloat16* Asrc = (s == 2) ? g_Alo : g_Ahi;
        const __nv_bfloat16* Bsrc = (s == 1) ? g_Wlo : g_Whi;
        const uint32_t base = sm_base + buf * FC_STAGE;
#pragma unroll
        for (int rep = 0; rep < 4; rep++) {
            int f = tid + rep * 256;
            if (f < 512) {
                int row = f >> 2, q = f & 3;
                cp_async16(base + row * ROWB + q * 16,
                           Asrc + (size_t)(m0 + row) * 512 + kloc + q * 8);
            } else {
                int g = f - 512;
                int row = g >> 2, q = g & 3;
                cp_async16(base + FC_BM * ROWB + row * ROWB + q * 16,
                           Bsrc + (size_t)(n0 + row) * 512 + kloc + q * 8);
            }
        }
        asm volatile("cp.async.commit_group;" ::: "memory");
    };

    // preload 3 stages
    load_stage(0, 0);
    load_stage(1, 1);
    load_stage(2, 2);

    for (int kc = 0; kc < 48; kc++) {
        const int buf = kc & 3;
        asm volatile("cp.async.wait_group 2;" ::: "memory");   // stage kc resident
        __syncthreads();                                       // + buf (kc+3)&3 free
        if (kc + 3 < 48) load_stage(kc + 3, (kc + 3) & 3);
        else asm volatile("cp.async.commit_group;" ::: "memory");  // keep count math

        const uint32_t aSm = sm_base + buf * FC_STAGE;
        const uint32_t bSm = aSm + FC_BM * ROWB;
#pragma unroll
        for (int ks = 0; ks < 2; ks++) {
            const int kofsA = ks * 32 + (lane >> 4) * 16;
            const int kofsB = ks * 32 + ((lane >> 3) & 1) * 16;
            uint32_t a[4][4];
#pragma unroll
            for (int mf = 0; mf < 4; mf++) {
                int row = mBase + mf * 16 + (lane & 15);
                ldmatrix_x4(a[mf][0], a[mf][1], a[mf][2], a[mf][3],
                            aSm + row * ROWB + kofsA);
            }
            uint32_t b[4][2];
#pragma unroll
            for (int nf2 = 0; nf2 < 2; nf2++) {
                int row = nBase + nf2 * 16 + (lane & 7) + ((lane >> 4) << 3);
                uint32_t r0, r1, r2, r3;
                ldmatrix_x4(r0, r1, r2, r3, bSm + row * ROWB + kofsB);
                b[nf2 * 2 + 0][0] = r0; b[nf2 * 2 + 0][1] = r1;
                b[nf2 * 2 + 1][0] = r2; b[nf2 * 2 + 1][1] = r3;
            }
#pragma unroll
            for (int mf = 0; mf < 4; mf++)
#pragma unroll
                for (int nf = 0; nf < 4; nf++)
                    mma16816(acc[mf][nf], a[mf], b[nf]);
        }
    }

    const int mrow = m0 + mBase + (lane >> 2);
    const int ncol = n0 + nBase + (lane & 3) * 2;
    float bb[4][2];
#pragma unroll
    for (int nf = 0; nf < 4; nf++) {
        bb[nf][0] = __ldg(&bias[ncol + nf * 8]);
        bb[nf][1] = __ldg(&bias[ncol + nf * 8 + 1]);
    }
#pragma unroll
    for (int mf = 0; mf < 4; mf++) {
        float* r0p = C + (size_t)(mrow + mf * 16) * VV + ncol;
        float* r1p = C + (size_t)(mrow + mf * 16 + 8) * VV + ncol;
#pragma unroll
        for (int nf = 0; nf < 4; nf++) {
            float2 v0 = {acc[mf][nf][0] + bb[nf][0], acc[mf][nf][1] + bb[nf][1]};
            float2 v1 = {acc[mf][nf][2] + bb[nf][0], acc[mf][nf][3] + bb[nf][1]};
            *(float2*)(r0p + nf * 8) = v0;
            *(float2*)(r1p + nf * 8) = v1;
        }
    }
}

// ---------------- h_last copy ----------------
__global__ void hlast_kernel(float* __restrict__ dst) {
    int t = threadIdx.x;
    if (t < BB * HH) dst[t] = g_h[t];
}

// ---------------- launch ----------------
extern "C" void kernel_launch(void* const* d_in, const int* in_sizes, int n_in,
                              void* d_out, int out_size) {
    const int*   x        = (const int*)  d_in[0];
    const float* h_in     = (const float*)d_in[1];
    const float* embed_W  = (const float*)d_in[2];
    const float* gru_w_ih = (const float*)d_in[3];
    const float* gru_b_ih = (const float*)d_in[4];
    const float* gru_w_hh = (const float*)d_in[5];
    const float* gru_b_hh = (const float*)d_in[6];
    const float* attn_w_W = (const float*)d_in[7];
    const float* attn_w_b = (const float*)d_in[8];
    const float* attn_u_W = (const float*)d_in[9];
    const float* attn_u_b = (const float*)d_in[10];
    const float* attn_v_W = (const float*)d_in[11];
    const float* attn_v_b = (const float*)d_in[12];
    const float* fc_W     = (const float*)d_in[13];
    const float* fc_b     = (const float*)d_in[14];
    float* out = (float*)d_out;

    float* d_xp;       cudaGetSymbolAddress((void**)&d_xp, g_xp);
    float* d_comb;     cudaGetSymbolAddress((void**)&d_comb, g_combined);
    float* d_q;        cudaGetSymbolAddress((void**)&d_q, g_q);
    float* d_k;        cudaGetSymbolAddress((void**)&d_k, g_k);

    cudaFuncSetAttribute(fc_mma_kernel, cudaFuncAttributeMaxDynamicSharedMemorySize,
                         FC_SMEM);

    // 0. W -> bf16 hi/lo split
    convW_kernel<<<(VV * 512) / 1024, 256>>>(fc_W);

    // 1. h0 <- input h
    init_kernel<<<1, 1024>>>(h_in);

    // 2. xp = embed_W[x] @ gru_w_ih^T + b_ih
    gemm_nt<<<dim3(768 / 64, BT / 64), 256>>>(embed_W, EE, x, gru_w_ih, EE,
                                              gru_b_ih, d_xp, 768);

    // 3. GRU scan: 4 clusters of 8 CTAs (writes combined[:, :256] + Ahi/Alo cols 0-255)
    gru_kernel<<<32, 256>>>(gru_w_hh, gru_b_hh);

    // 4. q, k projections
    gemm_nt<<<dim3(HH / 64, BT / 64), 256>>>(d_comb, 512, nullptr, attn_w_W, HH,
                                             attn_w_b, d_q, HH);
    gemm_nt<<<dim3(HH / 64, BT / 64), 256>>>(d_comb, 512, nullptr, attn_u_W, HH,
                                             attn_u_b, d_k, HH);

    // 5. attention (writes Ahi/Alo cols 256-511 directly)
    attn_kernel<<<dim3(TT / 8, BB), 256>>>(attn_v_W, attn_v_b);

    // 6. logits via HMMA (4-stage pipeline)
    fc_mma_kernel<<<dim3(VV / FC_BN, BT / FC_BM), 256, FC_SMEM>>>(fc_b, out);

    // 7. h_last
    hlast_kernel<<<1, 1024>>>(out + (size_t)out_size - BB * HH);
}

// round 17
// speedup vs baseline: 1.6149x; 1.6149x over previous
#include <cuda_runtime.h>
#include <cuda_bf16.h>
#include <cstdint>

// Problem constants
#define BB 4
#define TT 512
#define HH 256
#define EE 256
#define VV 32000
#define BT (BB*TT)          // 2048

// ---------------- device scratch (no cudaMalloc allowed) ----------------
__device__ float g_xp[BT * 768];          // [B*T, 3H]
__device__ float g_combined[BT * 512];    // [:, :256] = gru out
__device__ float g_q[BT * HH];
__device__ float g_k[BT * HH];
__device__ float g_h[BB * HH];            // h0 in, h_last out

// split-bf16 operands for the HMMA FC
__device__ __align__(256) __nv_bfloat16 g_Whi[(size_t)VV * 512];
__device__ __align__(256) __nv_bfloat16 g_Wlo[(size_t)VV * 512];
__device__ __align__(256) __nv_bfloat16 g_Ahi[(size_t)BT * 512];
__device__ __align__(256) __nv_bfloat16 g_Alo[(size_t)BT * 512];

typedef unsigned long long u64;

__device__ __forceinline__ float tanh_fast(float x) {
    float y; asm("tanh.approx.f32 %0, %1;" : "=f"(y) : "f"(x)); return y;
}
__device__ __forceinline__ uint32_t smem_u32(const void* p) {
    uint32_t a;
    asm("{ .reg .u64 t; cvta.to.shared.u64 t, %1; cvt.u32.u64 %0, t; }" : "=r"(a) : "l"(p));
    return a;
}
__device__ __forceinline__ u64 pack2(float lo, float hi) {
    u64 r; asm("mov.b64 %0, {%1,%2};" : "=l"(r) : "f"(lo), "f"(hi)); return r;
}
__device__ __forceinline__ void unpack2(u64 v, float& lo, float& hi) {
    asm("mov.b64 {%0,%1}, %2;" : "=f"(lo), "=f"(hi) : "l"(v));
}
__device__ __forceinline__ u64 ffma2(u64 a, u64 b, u64 c) {
    u64 d; asm("fma.rn.f32x2 %0, %1, %2, %3;" : "=l"(d) : "l"(a), "l"(b), "l"(c)); return d;
}

// ---------------- init: h0 <- input h ----------------
__global__ void init_kernel(const float* __restrict__ h_in) {
    int t = threadIdx.x;
    if (t < BB * HH) g_h[t] = h_in[t];
}

// ---------------- generic small GEMM: C[M,N] = A[M,K] @ B[N,K]^T + bias ----------------
__global__ void __launch_bounds__(256) gemm_nt(
    const float* __restrict__ A, int lda, const int* __restrict__ idx,
    const float* __restrict__ B, int K,
    const float* __restrict__ bias, float* __restrict__ C, int ldc)
{
    __shared__ float As[32 * 68];
    __shared__ float Bs[32 * 68];
    const int tid = threadIdx.x;
    const int m0 = blockIdx.y * 64, n0 = blockIdx.x * 64;
    const int tx = tid & 15, ty = tid >> 4;
    const int mt = ty * 4, nt = tx * 4;

    float acc[4][4];
#pragma unroll
    for (int i = 0; i < 4; i++)
#pragma unroll
        for (int j = 0; j < 4; j++) acc[i][j] = 0.f;

    const int kt_n = K >> 5;
    for (int kt = 0; kt < kt_n; kt++) {
        const int k0 = kt * 32;
#pragma unroll
        for (int rep = 0; rep < 2; rep++) {
            int f = tid + rep * 256;
            int row = f >> 3, kq = f & 7;
            int ar = m0 + row;
            if (idx) ar = __ldg(&idx[ar]);
            float4 av = __ldg((const float4*)(A + (size_t)ar * lda + k0 + kq * 4));
            float4 bv = __ldg((const float4*)(B + (size_t)(n0 + row) * K + k0 + kq * 4));
            As[(kq * 4 + 0) * 68 + row] = av.x;
            As[(kq * 4 + 1) * 68 + row] = av.y;
            As[(kq * 4 + 2) * 68 + row] = av.z;
            As[(kq * 4 + 3) * 68 + row] = av.w;
            Bs[(kq * 4 + 0) * 68 + row] = bv.x;
            Bs[(kq * 4 + 1) * 68 + row] = bv.y;
            Bs[(kq * 4 + 2) * 68 + row] = bv.z;
            Bs[(kq * 4 + 3) * 68 + row] = bv.w;
        }
        __syncthreads();
#pragma unroll
        for (int k = 0; k < 32; k++) {
            float4 a4 = *(const float4*)(As + k * 68 + mt);
            float4 b4 = *(const float4*)(Bs + k * 68 + nt);
            float am[4] = {a4.x, a4.y, a4.z, a4.w};
            float bn[4] = {b4.x, b4.y, b4.z, b4.w};
#pragma unroll
            for (int i = 0; i < 4; i++)
#pragma unroll
                for (int j = 0; j < 4; j++) acc[i][j] = fmaf(am[i], bn[j], acc[i][j]);
        }
        __syncthreads();
    }
    float4 b4 = __ldg((const float4*)(bias + n0 + nt));
#pragma unroll
    for (int i = 0; i < 4; i++) {
        float4 r;
        r.x = acc[i][0] + b4.x; r.y = acc[i][1] + b4.y;
        r.z = acc[i][2] + b4.z; r.w = acc[i][3] + b4.w;
        *(float4*)(C + (size_t)(m0 + mt + i) * ldc + n0 + nt) = r;
    }
}

// ---------------- GRU: 4 clusters x 8 CTAs, warp-local pipeline (R15 barrier) ----
// Thread (d, o): all 3 gates for dim d over cols [32o, 32o+32). In-warp octant
// reduction; o==0 lane does gate math + DSMEM broadcast; sync = barrier.cluster.
__global__ void __launch_bounds__(256, 1) __cluster_dims__(8, 1, 1)
gru_kernel(const float* __restrict__ w_hh, const float* __restrict__ b_hh)
{
    __shared__ __align__(16) float hsm[2][8 * 36];   // octant-strided, double-buffered

    const int tid = threadIdx.x;
    const int batch = blockIdx.x >> 3;
    const int rank = blockIdx.x & 7;
    const int d = tid >> 3;          // dim within CTA
    const int o = tid & 7;           // octant (32 cols)
    const int dim0 = rank * 32;

    // weights: 3 gates x 32 cols each, packed f32x2 (96 regs)
    u64 w2[48];
#pragma unroll
    for (int g = 0; g < 3; g++) {
        const float4* ws =
            (const float4*)(w_hh + (size_t)(g * 256 + dim0 + d) * 256 + o * 32);
#pragma unroll
        for (int c = 0; c < 8; c++) {
            float4 v = __ldg(&ws[c]);
            w2[g * 16 + 2 * c]     = pack2(v.x, v.y);
            w2[g * 16 + 2 * c + 1] = pack2(v.z, v.w);
        }
    }
    const float bhr = __ldg(&b_hh[0 * 256 + dim0 + d]);
    const float bhz = __ldg(&b_hh[1 * 256 + dim0 + d]);
    const float bhn = __ldg(&b_hh[2 * 256 + dim0 + d]);

    // initial h -> hsm[0]
    for (int idx = tid; idx < HH; idx += 256)
        hsm[0][(idx >> 5) * 36 + (idx & 31)] = g_h[batch * HH + idx];

    const int myd = dim0 + d;
    const int slot = (myd >> 5) * 36 + (myd & 31);
    float xr = 0.f, xz = 0.f, xn = 0.f;
    if (o == 0) {                    // prefetch xp for t=0
        const float* xp = g_xp + (size_t)(batch * TT) * 768 + myd;
        xr = __ldg(xp); xz = __ldg(xp + 256); xn = __ldg(xp + 512);
    }
    __syncthreads();

    for (int t = 0; t < TT; t++) {
        const int rb = t & 1, wb = rb ^ 1;

        // my 32-col slice of h: 8 conflict-free LDS.128
        u64 hv[16];
        {
            const ulonglong2* hs2 = (const ulonglong2*)(hsm[rb] + o * 36);
#pragma unroll
            for (int c = 0; c < 8; c++) {
                ulonglong2 p = hs2[c];
                hv[2 * c] = p.x; hv[2 * c + 1] = p.y;
            }
        }
        const float hold = hsm[rb][slot];

        u64 ar0 = 0, ar1 = 0, az0 = 0, az1 = 0, an0 = 0, an1 = 0;
#pragma unroll
        for (int c = 0; c < 16; c += 2) {
            ar0 = ffma2(w2[c],          hv[c],     ar0);
            ar1 = ffma2(w2[c + 1],      hv[c + 1], ar1);
            az0 = ffma2(w2[16 + c],     hv[c],     az0);
            az1 = ffma2(w2[16 + c + 1], hv[c + 1], az1);
            an0 = ffma2(w2[32 + c],     hv[c],     an0);
            an1 = ffma2(w2[32 + c + 1], hv[c + 1], an1);
        }
        float p0, p1, p2, p3;
        unpack2(ar0, p0, p1); unpack2(ar1, p2, p3);
        float sr = (p0 + p1) + (p2 + p3);
        unpack2(az0, p0, p1); unpack2(az1, p2, p3);
        float sz = (p0 + p1) + (p2 + p3);
        unpack2(an0, p0, p1); unpack2(an1, p2, p3);
        float sn = (p0 + p1) + (p2 + p3);
#pragma unroll
        for (int off = 1; off < 8; off <<= 1) {
            sr += __shfl_xor_sync(0xffffffffu, sr, off);
            sz += __shfl_xor_sync(0xffffffffu, sz, off);
            sn += __shfl_xor_sync(0xffffffffu, sn, off);
        }

        if (o == 0) {
            const float hr = sr + bhr, hz = sz + bhz, hn = sn + bhn;
            const float r = fmaf(0.5f, tanh_fast(0.5f * (xr + hr)), 0.5f);
            const float z = fmaf(0.5f, tanh_fast(0.5f * (xz + hz)), 0.5f);
            const float n = tanh_fast(fmaf(r, hn, xn));
            const float hnew = fmaf(z, hold - n, n);    // (1-z)*n + z*h
            const size_t row = (size_t)(batch * TT + t) * 512 + myd;
            g_combined[row] = hnew;
            // FC operands written directly (no convA kernel)
            const __nv_bfloat16 bh = __float2bfloat16(hnew);
            const __nv_bfloat16 bl = __float2bfloat16(hnew - __bfloat162float(bh));
            g_Ahi[row] = bh;
            g_Alo[row] = bl;

            // broadcast to hsm[wb] of all 8 cluster CTAs (disjoint slots)
            const uint32_t laddr = smem_u32(&hsm[wb][slot]);
#pragma unroll
            for (int pr = 0; pr < 8; pr++) {
                uint32_t raddr;
                asm("mapa.shared::cluster.u32 %0, %1, %2;"
                    : "=r"(raddr) : "r"(laddr), "r"(pr));
                asm volatile("st.shared::cluster.f32 [%0], %1;"
                             :: "r"(raddr), "f"(hnew));
            }
            if (t + 1 < TT) {                  // prefetch next xp
                const float* xp = g_xp + (size_t)(batch * TT + t + 1) * 768 + myd;
                xr = __ldg(xp); xz = __ldg(xp + 256); xn = __ldg(xp + 512);
            }
        }
        // cluster barrier: release my DSMEM stores, acquire peers'
        asm volatile("barrier.cluster.arrive.aligned;" ::: "memory");
        asm volatile("barrier.cluster.wait.aligned;" ::: "memory");
    }

    if (o == 0)                                // step TT lands in buffer 0
        g_h[batch * HH + myd] = hsm[0][slot];
}

// ---------------- attention (ctx written straight to Ahi/Alo) ----------------
__global__ void __launch_bounds__(256) attn_kernel(
    const float* __restrict__ vW, const float* __restrict__ vb)
{
    __shared__ float tile[16 * 256];
    __shared__ float sc[8][512];

    const int tid = threadIdx.x;
    const int w = tid >> 5, lane = tid & 31;
    const int b = blockIdx.y, it = blockIdx.x;
    const int i = it * 8 + w;

    const float4* q4 = (const float4*)(g_q + (size_t)(b * TT + i) * HH + lane * 8);
    const float4 q0 = __ldg(q4), q1 = __ldg(q4 + 1);
    const float4* v4 = (const float4*)(vW + lane * 8);
    const float4 v0 = __ldg(v4), v1 = __ldg(v4 + 1);
    const float vbias = __ldg(vb);

    const int imax = it * 8 + 7;
    const int ntiles = (imax >> 4) + 1;

    for (int jt = 0; jt < ntiles; jt++) {
        const int j0 = jt * 16;
        float4* t4 = (float4*)tile;
#pragma unroll
        for (int rep = 0; rep < 4; rep++) {
            int f = tid + rep * 256;
            int row = f >> 6, c4 = f & 63;
            t4[f] = __ldg((const float4*)g_k + (size_t)(b * TT + j0 + row) * 64 + c4);
        }
        __syncthreads();
#pragma unroll 4
        for (int jj = 0; jj < 16; jj++) {
            int j = j0 + jj;
            if (j <= i) {
                const float4* kr = (const float4*)(tile + jj * 256) + lane * 2;
                float4 k0 = kr[0], k1 = kr[1];
                float s;
                s = v0.x * tanh_fast(q0.x + k0.x);
                s = fmaf(v0.y, tanh_fast(q0.y + k0.y), s);
                s = fmaf(v0.z, tanh_fast(q0.z + k0.z), s);
                s = fmaf(v0.w, tanh_fast(q0.w + k0.w), s);
                s = fmaf(v1.x, tanh_fast(q1.x + k1.x), s);
                s = fmaf(v1.y, tanh_fast(q1.y + k1.y), s);
                s = fmaf(v1.z, tanh_fast(q1.z + k1.z), s);
                s = fmaf(v1.w, tanh_fast(q1.w + k1.w), s);
#pragma unroll
                for (int o = 16; o > 0; o >>= 1) s += __shfl_xor_sync(0xffffffffu, s, o);
                if (lane == 0) sc[w][j] = s + vbias;
            }
        }
        __syncthreads();
    }

    float m = -1e30f;
    for (int j = lane; j <= i; j += 32) m = fmaxf(m, sc[w][j]);
#pragma unroll
    for (int o = 16; o > 0; o >>= 1) m = fmaxf(m, __shfl_xor_sync(0xffffffffu, m, o));
    float sum = 0.f;
    for (int j = lane; j <= i; j += 32) {
        float p = __expf(sc[w][j] - m);
        sc[w][j] = p;
        sum += p;
    }
#pragma unroll
    for (int o = 16; o > 0; o >>= 1) sum += __shfl_xor_sync(0xffffffffu, sum, o);
    const float inv = 1.f / sum;
    __syncthreads();

    float a0 = 0, a1 = 0, a2 = 0, a3 = 0, a4 = 0, a5 = 0, a6 = 0, a7 = 0;
    for (int jt = 0; jt < ntiles; jt++) {
        const int j0 = jt * 16;
        float4* t4 = (float4*)tile;
#pragma unroll
        for (int rep = 0; rep < 4; rep++) {
            int f = tid + rep * 256;
            int row = f >> 6, c4 = f & 63;
            t4[f] = __ldg((const float4*)g_combined + (size_t)(b * TT + j0 + row) * 128 + c4);
        }
        __syncthreads();
#pragma unroll 4
        for (int jj = 0; jj < 16; jj++) {
            int j = j0 + jj;
            if (j <= i) {
                float p = sc[w][j];
                const float4* orow = (const float4*)(tile + jj * 256) + lane * 2;
                float4 o0 = orow[0], o1 = orow[1];
                a0 = fmaf(p, o0.x, a0); a1 = fmaf(p, o0.y, a1);
                a2 = fmaf(p, o0.z, a2); a3 = fmaf(p, o0.w, a3);
                a4 = fmaf(p, o1.x, a4); a5 = fmaf(p, o1.y, a5);
                a6 = fmaf(p, o1.z, a6); a7 = fmaf(p, o1.w, a7);
            }
        }
        __syncthreads();
    }
    float vals[8] = {a0 * inv, a1 * inv, a2 * inv, a3 * inv,
                     a4 * inv, a5 * inv, a6 * inv, a7 * inv};
    __nv_bfloat16 hi[8], lo[8];
#pragma unroll
    for (int j = 0; j < 8; j++) {
        hi[j] = __float2bfloat16(vals[j]);
        lo[j] = __float2bfloat16(vals[j] - __bfloat162float(hi[j]));
    }
    const size_t off = (size_t)(b * TT + i) * 512 + 256 + lane * 8;
    *(uint4*)(g_Ahi + off) = *(uint4*)hi;
    *(uint4*)(g_Alo + off) = *(uint4*)lo;
}

// ---------------- W split-bf16 conversion ----------------
__global__ void __launch_bounds__(256) convW_kernel(const float* __restrict__ W) {
    size_t i = ((size_t)blockIdx.x * 256 + threadIdx.x) * 4;
    float4 v = __ldg((const float4*)(W + i));
    __nv_bfloat16 h[4], l[4];
    float x[4] = {v.x, v.y, v.z, v.w};
#pragma unroll
    for (int j = 0; j < 4; j++) {
        h[j] = __float2bfloat16(x[j]);
        l[j] = __float2bfloat16(x[j] - __bfloat162float(h[j]));
    }
    *(uint2*)(g_Whi + i) = *(uint2*)h;
    *(uint2*)(g_Wlo + i) = *(uint2*)l;
}

// ---------------- FC via mma.sync HMMA, fused 3-term k-chunks ----------------
// C = Ahi@Whi^T + Ahi@Wlo^T + Alo@Whi^T + bias.  16 k-chunks of 32; stage holds
// {Ahi, Alo, Whi, Wlo} tiles; fragments loaded once, reused across the 3 terms:
// 2/3 the smem/global traffic of the 48-stage version at identical MMA count.
// CTA 128x128, 256 threads, warp tile 64x32, 2-stage ring, 2 CTAs/SM.
#define FC_BM 128
#define FC_BN 128
#define ROWB 80
#define FC_TILE (128 * ROWB)                   // 10240
#define FC_STAGE (4 * FC_TILE)                 // 40960
#define FC_SMEM (2 * FC_STAGE)                 // 81920

__device__ __forceinline__ void ldmatrix_x4(uint32_t& r0, uint32_t& r1, uint32_t& r2,
                                            uint32_t& r3, uint32_t addr) {
    asm volatile("ldmatrix.sync.aligned.m8n8.x4.shared.b16 {%0,%1,%2,%3}, [%4];"
                 : "=r"(r0), "=r"(r1), "=r"(r2), "=r"(r3) : "r"(addr));
}
__device__ __forceinline__ void mma16816(float* d, const uint32_t* a, const uint32_t* b) {
    asm volatile(
        "mma.sync.aligned.m16n8k16.row.col.f32.bf16.bf16.f32 "
        "{%0,%1,%2,%3}, {%4,%5,%6,%7}, {%8,%9}, {%0,%1,%2,%3};"
        : "+f"(d[0]), "+f"(d[1]), "+f"(d[2]), "+f"(d[3])
        : "r"(a[0]), "r"(a[1]), "r"(a[2]), "r"(a[3]), "r"(b[0]), "r"(b[1]));
}
__device__ __forceinline__ void cp_async16(uint32_t dst, const void* src) {
    asm volatile("cp.async.cg.shared.global [%0], [%1], 16;" :: "r"(dst), "l"(src));
}

__global__ void __launch_bounds__(256, 2) fc_mma_kernel(
    const float* __restrict__ bias, float* __restrict__ C)
{
    extern __shared__ __align__(128) char smem[];
    const int tid = threadIdx.x;
    const int lane = tid & 31, warp = tid >> 5;
    const int wm = warp >> 2, wn = warp & 3;
    const int mBase = wm * 64, nBase = wn * 32;
    const int m0 = blockIdx.y * FC_BM, n0 = blockIdx.x * FC_BN;
    const uint32_t sm_base = smem_u32(smem);

    float acc[4][4][4];
#pragma unroll
    for (int i = 0; i < 4; i++)
#pragma unroll
        for (int j = 0; j < 4; j++)
#pragma unroll
            for (int r = 0; r < 4; r++) acc[i][j][r] = 0.f;

    // stage fill: 4 tiles x 512 16B-chunks; tile t spans reps 2t, 2t+1
    auto load_stage = [&](int kc, int buf) {
        const int kloc = kc * 32;
        const uint32_t base = sm_base + buf * FC_STAGE;
        const int row = (tid & 127) >> 1;          // not used; placeholder removed
        (void)row;
#pragma unroll
        for (int rep = 0; rep < 8; rep++) {
            const int f = tid + rep * 256;
            const int tile = f >> 9;               // compile-time per rep
            const int g = f & 511;
            const int r = g >> 2, q = g & 3;
            const __nv_bfloat16* src;
            if (tile == 0)      src = g_Ahi + (size_t)(m0 + r) * 512 + kloc + q * 8;
            else if (tile == 1) src = g_Alo + (size_t)(m0 + r) * 512 + kloc + q * 8;
            else if (tile == 2) src = g_Whi + (size_t)(n0 + r) * 512 + kloc + q * 8;
            else                src = g_Wlo + (size_t)(n0 + r) * 512 + kloc + q * 8;
            cp_async16(base + tile * FC_TILE + r * ROWB + q * 16, src);
        }
        asm volatile("cp.async.commit_group;" ::: "memory");
    };

    load_stage(0, 0);

    for (int kc = 0; kc < 16; kc++) {
        const int buf = kc & 1;
        __syncthreads();                           // all warps done with buf
        if (kc + 1 < 16) {
            load_stage(kc + 1, buf ^ 1);
            asm volatile("cp.async.wait_group 1;" ::: "memory");
        } else {
            asm volatile("cp.async.wait_group 0;" ::: "memory");
        }
        __syncthreads();                           // stage kc visible

        const uint32_t sAhi = sm_base + buf * FC_STAGE;
        const uint32_t sAlo = sAhi + FC_TILE;
        const uint32_t sWhi = sAhi + 2 * FC_TILE;
        const uint32_t sWlo = sAhi + 3 * FC_TILE;
#pragma unroll
        for (int ks = 0; ks < 2; ks++) {
            const int kofsA = ks * 32 + (lane >> 4) * 16;
            const int kofsB = ks * 32 + ((lane >> 3) & 1) * 16;
            uint32_t bhi[4][2], blo[4][2];
#pragma unroll
            for (int nf2 = 0; nf2 < 2; nf2++) {
                const int row = nBase + nf2 * 16 + (lane & 7) + ((lane >> 4) << 3);
                uint32_t r0, r1, r2, r3;
                ldmatrix_x4(r0, r1, r2, r3, sWhi + row * ROWB + kofsB);
                bhi[nf2 * 2 + 0][0] = r0; bhi[nf2 * 2 + 0][1] = r1;
                bhi[nf2 * 2 + 1][0] = r2; bhi[nf2 * 2 + 1][1] = r3;
                ldmatrix_x4(r0, r1, r2, r3, sWlo + row * ROWB + kofsB);
                blo[nf2 * 2 + 0][0] = r0; blo[nf2 * 2 + 0][1] = r1;
                blo[nf2 * 2 + 1][0] = r2; blo[nf2 * 2 + 1][1] = r3;
            }
#pragma unroll
            for (int mf = 0; mf < 4; mf++) {
                const int rowA = mBase + mf * 16 + (lane & 15);
                uint32_t ah[4], al[4];
                ldmatrix_x4(ah[0], ah[1], ah[2], ah[3], sAhi + rowA * ROWB + kofsA);
                ldmatrix_x4(al[0], al[1], al[2], al[3], sAlo + rowA * ROWB + kofsA);
#pragma unroll
                for (int nf = 0; nf < 4; nf++) {
                    mma16816(acc[mf][nf], ah, bhi[nf]);
                    mma16816(acc[mf][nf], ah, blo[nf]);
                    mma16816(acc[mf][nf], al, bhi[nf]);
                }
            }
        }
    }

    const int mrow = m0 + mBase + (lane >> 2);
    const int ncol = n0 + nBase + (lane & 3) * 2;
    float bb[4][2];
#pragma unroll
    for (int nf = 0; nf < 4; nf++) {
        bb[nf][0] = __ldg(&bias[ncol + nf * 8]);
        bb[nf][1] = __ldg(&bias[ncol + nf * 8 + 1]);
    }
#pragma unroll
    for (int mf = 0; mf < 4; mf++) {
        float* r0p = C + (size_t)(mrow + mf * 16) * VV + ncol;
        float* r1p = C + (size_t)(mrow + mf * 16 + 8) * VV + ncol;
#pragma unroll
        for (int nf = 0; nf < 4; nf++) {
            float2 v0 = {acc[mf][nf][0] + bb[nf][0], acc[mf][nf][1] + bb[nf][1]};
            float2 v1 = {acc[mf][nf][2] + bb[nf][0], acc[mf][nf][3] + bb[nf][1]};
            *(float2*)(r0p + nf * 8) = v0;
            *(float2*)(r1p + nf * 8) = v1;
        }
    }
}

// ---------------- h_last copy ----------------
__global__ void hlast_kernel(float* __restrict__ dst) {
    int t = threadIdx.x;
    if (t < BB * HH) dst[t] = g_h[t];
}

// ---------------- launch ----------------
extern "C" void kernel_launch(void* const* d_in, const int* in_sizes, int n_in,
                              void* d_out, int out_size) {
    const int*   x        = (const int*)  d_in[0];
    const float* h_in     = (const float*)d_in[1];
    const float* embed_W  = (const float*)d_in[2];
    const float* gru_w_ih = (const float*)d_in[3];
    const float* gru_b_ih = (const float*)d_in[4];
    const float* gru_w_hh = (const float*)d_in[5];
    const float* gru_b_hh = (const float*)d_in[6];
    const float* attn_w_W = (const float*)d_in[7];
    const float* attn_w_b = (const float*)d_in[8];
    const float* attn_u_W = (const float*)d_in[9];
    const float* attn_u_b = (const float*)d_in[10];
    const float* attn_v_W = (const float*)d_in[11];
    const float* attn_v_b = (const float*)d_in[12];
    const float* fc_W     = (const float*)d_in[13];
    const float* fc_b     = (const float*)d_in[14];
    float* out = (float*)d_out;

    float* d_xp;       cudaGetSymbolAddress((void**)&d_xp, g_xp);
    float* d_comb;     cudaGetSymbolAddress((void**)&d_comb, g_combined);
    float* d_q;        cudaGetSymbolAddress((void**)&d_q, g_q);
    float* d_k;        cudaGetSymbolAddress((void**)&d_k, g_k);

    cudaFuncSetAttribute(fc_mma_kernel, cudaFuncAttributeMaxDynamicSharedMemorySize,
                         FC_SMEM);

    // 0. W -> bf16 hi/lo split
    convW_kernel<<<(VV * 512) / 1024, 256>>>(fc_W);

    // 1. h0 <- input h
    init_kernel<<<1, 1024>>>(h_in);

    // 2. xp = embed_W[x] @ gru_w_ih^T + b_ih
    gemm_nt<<<dim3(768 / 64, BT / 64), 256>>>(embed_W, EE, x, gru_w_ih, EE,
                                              gru_b_ih, d_xp, 768);

    // 3. GRU scan: 4 clusters of 8 CTAs (writes combined[:, :256] + Ahi/Alo cols 0-255)
    gru_kernel<<<32, 256>>>(gru_w_hh, gru_b_hh);

    // 4. q, k projections
    gemm_nt<<<dim3(HH / 64, BT / 64), 256>>>(d_comb, 512, nullptr, attn_w_W, HH,
                                             attn_w_b, d_q, HH);
    gemm_nt<<<dim3(HH / 64, BT / 64), 256>>>(d_comb, 512, nullptr, attn_u_W, HH,
                                             attn_u_b, d_k, HH);

    // 5. attention (writes Ahi/Alo cols 256-511 directly)
    attn_kernel<<<dim3(TT / 8, BB), 256>>>(attn_v_W, attn_v_b);

    // 6. logits via fused 3-term HMMA
    fc_mma_kernel<<<dim3(VV / FC_BN, BT / FC_BM), 256, FC_SMEM>>>(fc_b, out);

    // 7. h_last
    hlast_kernel<<<1, 1024>>>(out + (size_t)out_size - BB * HH);
}